// round 1
// baseline (speedup 1.0000x reference)
#include <cuda_runtime.h>
#include <math.h>

// Problem constants
#define TS   1024
#define BS   64
#define HID  512
#define G4   2048
#define NCTA 128
#define TBH  ((size_t)TS * BS * HID)   // 33554432
#define BH   (BS * HID)                // 32768
#define LSTM_SMEM (32 * 516 * 4)       // 66048 bytes, padded h tile

// Scratch (device globals are the sanctioned allocation-free workaround)
__device__ float g_xgates[(size_t)TS * BS * G4];   // 512 MB: precomputed input gates
__device__ float g_out1[(size_t)TS * BS * HID];    // 128 MB: layer-0 output sequence
__device__ float g_hbuf[2][BH];                    // double-buffered hidden state
__device__ unsigned int g_bar;                     // grid barrier counter

__global__ void reset_kernel() { g_bar = 0u; }

// ---------------------------------------------------------------------------
// Input projection GEMM: C[m,g] = sum_k A[m,k] * W[g,k] + b1[g] + b2[g]
// A: [65536 x 512] row-major, W: [2048 x 512] row-major (NT gemm, K-contiguous)
// Tile 128x128x16, 256 threads, 8x8 per thread. Writes g_xgates.
// ---------------------------------------------------------------------------
__global__ __launch_bounds__(256, 2) void gemm_xg(
    const float* __restrict__ A,
    const float* __restrict__ W,
    const float* __restrict__ b1,
    const float* __restrict__ b2)
{
    __shared__ float As[16][128];
    __shared__ float Bs[16][128];
    const int tid = threadIdx.x;
    const int m0 = blockIdx.y * 128;
    const int n0 = blockIdx.x * 128;
    const int tx = tid & 15, ty = tid >> 4;
    const int lr = tid >> 2;          // 0..63: row within half-tile
    const int lk = (tid & 3) << 2;    // 0,4,8,12: k offset

    const float* Ap = A + (size_t)(m0 + lr) * HID + lk;
    const float* Wp = W + (size_t)(n0 + lr) * HID + lk;

    float acc[8][8];
#pragma unroll
    for (int i = 0; i < 8; i++)
#pragma unroll
        for (int j = 0; j < 8; j++) acc[i][j] = 0.f;

    for (int k0 = 0; k0 < HID; k0 += 16) {
        float4 a0 = *(const float4*)(Ap + k0);
        float4 a1 = *(const float4*)(Ap + (size_t)64 * HID + k0);
        float4 w0 = *(const float4*)(Wp + k0);
        float4 w1 = *(const float4*)(Wp + (size_t)64 * HID + k0);
        __syncthreads();
        As[lk + 0][lr] = a0.x; As[lk + 1][lr] = a0.y; As[lk + 2][lr] = a0.z; As[lk + 3][lr] = a0.w;
        As[lk + 0][lr + 64] = a1.x; As[lk + 1][lr + 64] = a1.y; As[lk + 2][lr + 64] = a1.z; As[lk + 3][lr + 64] = a1.w;
        Bs[lk + 0][lr] = w0.x; Bs[lk + 1][lr] = w0.y; Bs[lk + 2][lr] = w0.z; Bs[lk + 3][lr] = w0.w;
        Bs[lk + 0][lr + 64] = w1.x; Bs[lk + 1][lr + 64] = w1.y; Bs[lk + 2][lr + 64] = w1.z; Bs[lk + 3][lr + 64] = w1.w;
        __syncthreads();
#pragma unroll
        for (int k = 0; k < 16; k++) {
            float a[8], bb[8];
            *(float4*)&a[0]  = *(const float4*)&As[k][ty * 8];
            *(float4*)&a[4]  = *(const float4*)&As[k][ty * 8 + 4];
            *(float4*)&bb[0] = *(const float4*)&Bs[k][tx * 8];
            *(float4*)&bb[4] = *(const float4*)&Bs[k][tx * 8 + 4];
#pragma unroll
            for (int i = 0; i < 8; i++)
#pragma unroll
                for (int j = 0; j < 8; j++) acc[i][j] += a[i] * bb[j];
        }
    }

    float bias[8];
#pragma unroll
    for (int u = 0; u < 8; u++) {
        int col = n0 + tx * 8 + u;
        bias[u] = b1[col] + b2[col];
    }
#pragma unroll
    for (int r = 0; r < 8; r++) {
        size_t m = (size_t)(m0 + ty * 8 + r);
        float* Cp = g_xgates + m * G4 + n0 + tx * 8;
        float4 v0, v1;
        v0.x = acc[r][0] + bias[0]; v0.y = acc[r][1] + bias[1];
        v0.z = acc[r][2] + bias[2]; v0.w = acc[r][3] + bias[3];
        v1.x = acc[r][4] + bias[4]; v1.y = acc[r][5] + bias[5];
        v1.z = acc[r][6] + bias[6]; v1.w = acc[r][7] + bias[7];
        *(float4*)Cp = v0;
        *(float4*)(Cp + 4) = v1;
    }
}

// ---------------------------------------------------------------------------
// Persistent recurrence kernel. 128 CTAs x 256 threads, all co-resident.
// Thread (warp w -> j, lane -> b) owns one (b, j) cell: c stays in a register
// for all T steps; 4 dot products per step against smem-staged h slice.
// h is double-buffered in global memory; loads via __ldcg (L2) because L1 is
// not coherent with writes from other SMs. One grid barrier per timestep.
// ---------------------------------------------------------------------------
__device__ __forceinline__ float sigmoidf_(float x) { return 1.f / (1.f + expf(-x)); }

__global__ __launch_bounds__(256, 1) void lstm_kernel(
    const float* __restrict__ Whh,   // [4H][H] for this layer
    const float* __restrict__ h0,    // [B][H]
    const float* __restrict__ c0,    // [B][H]
    float* __restrict__ out,         // [T][B][H]
    float* __restrict__ hn,          // [B][H]
    float* __restrict__ cn)          // [B][H]
{
    extern __shared__ float h_sm[];  // [32][516] padded (stride 516 -> conflict-free LDS.128)
    const int tid  = threadIdx.x;
    const int cta  = blockIdx.x;
    const int jb   = cta & 63;       // 64 j-blocks of 8
    const int bb   = cta >> 6;       // 2 b-blocks of 32
    const int w    = tid >> 5;       // warp -> j within block
    const int lane = tid & 31;       // lane -> b within block
    const int j    = jb * 8 + w;
    const int b    = bb * 32 + lane;
    const int bj   = b * HID + j;

    const float4* Wi = (const float4*)(Whh + (size_t)(0 * HID + j) * HID);
    const float4* Wf = (const float4*)(Whh + (size_t)(1 * HID + j) * HID);
    const float4* Wg = (const float4*)(Whh + (size_t)(2 * HID + j) * HID);
    const float4* Wo = (const float4*)(Whh + (size_t)(3 * HID + j) * HID);

    float c = c0[bj];
    __stcg(&g_hbuf[0][bj], h0[bj]);

    unsigned expect = 0;
    // barrier: make h_buf[0] init visible before step 0 reads
    __syncthreads();
    if (tid == 0) {
        __threadfence();
        atomicAdd(&g_bar, 1u);
        expect += NCTA;
        while (*((volatile unsigned*)&g_bar) < expect) { }
        __threadfence();
    }
    __syncthreads();

    float h = 0.f;
    for (int t = 0; t < TS; t++) {
        const float* hcur = g_hbuf[t & 1];
        // stage this CTA's 32-batch slice of h into smem (L2 loads, coalesced)
#pragma unroll
        for (int idx = tid; idx < 32 * 128; idx += 256) {
            int r  = idx >> 7;
            int c4 = idx & 127;
            float4 v = __ldcg((const float4*)(hcur + (size_t)(bb * 32 + r) * HID) + c4);
            *(float4*)&h_sm[r * 516 + c4 * 4] = v;
        }
        __syncthreads();

        const float* xgt = g_xgates + ((size_t)t * BS + b) * G4;
        float ai = xgt[j];
        float af = xgt[HID + j];
        float ag = xgt[2 * HID + j];
        float ao = xgt[3 * HID + j];

        const float4* hp = (const float4*)&h_sm[lane * 516];
#pragma unroll 8
        for (int i = 0; i < 128; i++) {
            float4 hv = hp[i];
            float4 wi = Wi[i], wf = Wf[i], wg = Wg[i], wo = Wo[i];
            ai += hv.x * wi.x + hv.y * wi.y + hv.z * wi.z + hv.w * wi.w;
            af += hv.x * wf.x + hv.y * wf.y + hv.z * wf.z + hv.w * wf.w;
            ag += hv.x * wg.x + hv.y * wg.y + hv.z * wg.z + hv.w * wg.w;
            ao += hv.x * wo.x + hv.y * wo.y + hv.z * wo.z + hv.w * wo.w;
        }

        float ig = sigmoidf_(ai);
        float fg = sigmoidf_(af);
        float gg = tanhf(ag);
        float og = sigmoidf_(ao);
        c = fg * c + ig * gg;
        h = og * tanhf(c);

        out[((size_t)t * BS + b) * HID + j] = h;
        __stcg(&g_hbuf[(t + 1) & 1][bj], h);

        // grid barrier: all writes of step t visible before step t+1 reads
        __syncthreads();
        if (tid == 0) {
            __threadfence();
            atomicAdd(&g_bar, 1u);
            expect += NCTA;
            while (*((volatile unsigned*)&g_bar) < expect) { }
            __threadfence();
        }
        __syncthreads();
    }

    hn[bj] = h;
    cn[bj] = c;
}

// ---------------------------------------------------------------------------
// Launch: per layer {gemm -> reset barrier -> persistent recurrence}.
// Output layout: [layer_out (T,B,H)][h_n (L,B,H)][c_n (L,B,H)]
// ---------------------------------------------------------------------------
extern "C" void kernel_launch(void* const* d_in, const int* in_sizes, int n_in,
                              void* d_out, int out_size)
{
    const float* x    = (const float*)d_in[0];
    const float* h0   = (const float*)d_in[1];
    const float* c0   = (const float*)d_in[2];
    const float* W_ih = (const float*)d_in[3];
    const float* W_hh = (const float*)d_in[4];
    const float* b_ih = (const float*)d_in[5];
    const float* b_hh = (const float*)d_in[6];
    float* out = (float*)d_out;

    cudaFuncSetAttribute(lstm_kernel, cudaFuncAttributeMaxDynamicSharedMemorySize, LSTM_SMEM);

    void* p_out1_v = nullptr;
    cudaGetSymbolAddress(&p_out1_v, g_out1);
    float* p_out1 = (float*)p_out1_v;

    dim3 ggrid(G4 / 128, (TS * BS) / 128);   // (16, 512)

    // Layer 0
    reset_kernel<<<1, 1>>>();
    gemm_xg<<<ggrid, 256>>>(x, W_ih, b_ih, b_hh);
    lstm_kernel<<<NCTA, 256, LSTM_SMEM>>>(
        W_hh, h0, c0,
        p_out1,
        out + TBH,                       // h_n[0]
        out + TBH + 2 * (size_t)BH);     // c_n[0]

    // Layer 1
    reset_kernel<<<1, 1>>>();
    gemm_xg<<<ggrid, 256>>>(p_out1, W_ih + (size_t)G4 * HID, b_ih + G4, b_hh + G4);
    lstm_kernel<<<NCTA, 256, LSTM_SMEM>>>(
        W_hh + (size_t)G4 * HID, h0 + BH, c0 + BH,
        out,                             // final layer_out
        out + TBH + (size_t)BH,          // h_n[1]
        out + TBH + 3 * (size_t)BH);     // c_n[1]

    (void)in_sizes; (void)n_in; (void)out_size;
}

// round 2
// speedup vs baseline: 1.5919x; 1.5919x over previous
#include <cuda_runtime.h>
#include <math.h>

// Problem constants
#define TS   1024
#define BS   64
#define HID  512
#define G4   2048
#define NCTA 128
#define MROWS 65536                    // T*B rows of the projection GEMM
#define TBH  ((size_t)TS * BS * HID)   // 33554432
#define BH   (BS * HID)                // 32768
// smem: h tile [32][516] padded + W_hh slice [4][8][512]
#define LSTM_SMEM ((32 * 516 + 4 * 8 * 512) * 4)   // 131584 bytes

// Scratch (device globals: the sanctioned allocation-free path)
__device__ float g_xgates[(size_t)G4 * MROWS];     // 512 MB, TRANSPOSED [col][row]
__device__ float g_out1[(size_t)TS * BS * HID];    // 128 MB: layer-0 output sequence
__device__ float g_hbuf[2][BH];                    // double-buffered hidden state
__device__ unsigned int g_bar;                     // grid barrier counter

__global__ void reset_kernel() { g_bar = 0u; }

// ---- packed f32x2 helpers (sm_100+ PTX) -----------------------------------
__device__ __forceinline__ unsigned long long fma2(unsigned long long a,
                                                   unsigned long long b,
                                                   unsigned long long c) {
    unsigned long long d;
    asm("fma.rn.f32x2 %0, %1, %2, %3;" : "=l"(d) : "l"(a), "l"(b), "l"(c));
    return d;
}
__device__ __forceinline__ unsigned long long pack2(float x, float y) {
    unsigned long long d;
    asm("mov.b64 %0, {%1, %2};" : "=l"(d) : "f"(x), "f"(y));
    return d;
}
__device__ __forceinline__ float2 unpack2(unsigned long long v) {
    float2 r;
    asm("mov.b64 {%0, %1}, %2;" : "=f"(r.x), "=f"(r.y) : "l"(v));
    return r;
}

// ---------------------------------------------------------------------------
// Input projection GEMM: C_T[g][m] = sum_k A[m,k] * W[g,k] + b1[g] + b2[g]
// A: [65536 x 512] row-major, W: [2048 x 512] row-major (NT gemm).
// Tile 128x128x16, 256 threads, 8x8 per thread, FFMA2 inner product.
// Output stored TRANSPOSED (col-major) so the recurrence reads coalesced.
// ---------------------------------------------------------------------------
__global__ __launch_bounds__(256, 2) void gemm_xg(
    const float* __restrict__ A,
    const float* __restrict__ W,
    const float* __restrict__ b1,
    const float* __restrict__ b2)
{
    __shared__ float As[16][128];
    __shared__ float Bs[16][128];
    const int tid = threadIdx.x;
    const int m0 = blockIdx.y * 128;
    const int n0 = blockIdx.x * 128;
    const int tx = tid & 15, ty = tid >> 4;
    const int lr = tid >> 2;          // 0..63: row within half-tile
    const int lk = (tid & 3) << 2;    // 0,4,8,12: k offset

    const float* Ap = A + (size_t)(m0 + lr) * HID + lk;
    const float* Wp = W + (size_t)(n0 + lr) * HID + lk;

    unsigned long long acc2[8][4];    // [row][col-pair], packed over adjacent cols
#pragma unroll
    for (int i = 0; i < 8; i++)
#pragma unroll
        for (int j = 0; j < 4; j++) acc2[i][j] = 0ull;   // (0.f, 0.f)

    for (int k0 = 0; k0 < HID; k0 += 16) {
        float4 a0 = *(const float4*)(Ap + k0);
        float4 a1 = *(const float4*)(Ap + (size_t)64 * HID + k0);
        float4 w0 = *(const float4*)(Wp + k0);
        float4 w1 = *(const float4*)(Wp + (size_t)64 * HID + k0);
        __syncthreads();
        As[lk + 0][lr] = a0.x; As[lk + 1][lr] = a0.y; As[lk + 2][lr] = a0.z; As[lk + 3][lr] = a0.w;
        As[lk + 0][lr + 64] = a1.x; As[lk + 1][lr + 64] = a1.y; As[lk + 2][lr + 64] = a1.z; As[lk + 3][lr + 64] = a1.w;
        Bs[lk + 0][lr] = w0.x; Bs[lk + 1][lr] = w0.y; Bs[lk + 2][lr] = w0.z; Bs[lk + 3][lr] = w0.w;
        Bs[lk + 0][lr + 64] = w1.x; Bs[lk + 1][lr + 64] = w1.y; Bs[lk + 2][lr + 64] = w1.z; Bs[lk + 3][lr + 64] = w1.w;
        __syncthreads();
#pragma unroll
        for (int k = 0; k < 16; k++) {
            float a[8];
            *(float4*)&a[0] = *(const float4*)&As[k][ty * 8];
            *(float4*)&a[4] = *(const float4*)&As[k][ty * 8 + 4];
            const ulonglong2* bp = (const ulonglong2*)&Bs[k][tx * 8];
            ulonglong2 t0 = bp[0];
            ulonglong2 t1 = bp[1];
#pragma unroll
            for (int i = 0; i < 8; i++) {
                unsigned long long ad = pack2(a[i], a[i]);
                acc2[i][0] = fma2(ad, t0.x, acc2[i][0]);
                acc2[i][1] = fma2(ad, t0.y, acc2[i][1]);
                acc2[i][2] = fma2(ad, t1.x, acc2[i][2]);
                acc2[i][3] = fma2(ad, t1.y, acc2[i][3]);
            }
        }
    }

    // unpack to column-major values + bias, store transposed (contiguous in m)
    float val[8][8];                  // [row][col]
#pragma unroll
    for (int i = 0; i < 8; i++)
#pragma unroll
        for (int jp = 0; jp < 4; jp++) {
            float2 p = unpack2(acc2[i][jp]);
            val[i][2 * jp] = p.x;
            val[i][2 * jp + 1] = p.y;
        }
#pragma unroll
    for (int u = 0; u < 8; u++) {
        int col = n0 + tx * 8 + u;
        float bias = b1[col] + b2[col];
        float* Cp = g_xgates + (size_t)col * MROWS + m0 + ty * 8;
        float4 lo, hi;
        lo.x = val[0][u] + bias; lo.y = val[1][u] + bias;
        lo.z = val[2][u] + bias; lo.w = val[3][u] + bias;
        hi.x = val[4][u] + bias; hi.y = val[5][u] + bias;
        hi.z = val[6][u] + bias; hi.w = val[7][u] + bias;
        *(float4*)Cp = lo;
        *(float4*)(Cp + 4) = hi;
    }
}

// ---------------------------------------------------------------------------
// Persistent recurrence. 128 CTAs x 256 threads. W_hh slice cached in smem
// (loaded once), c stays in a register for all T steps, FFMA2 dot products.
// h double-buffered in global (L2 via __ldcg/__stcg for cross-SM coherence).
// ---------------------------------------------------------------------------
__device__ __forceinline__ float sigmoidf_(float x) { return 1.f / (1.f + expf(-x)); }

__global__ __launch_bounds__(256, 1) void lstm_kernel(
    const float* __restrict__ Whh,   // [4H][H] for this layer
    const float* __restrict__ h0,    // [B][H]
    const float* __restrict__ c0,    // [B][H]
    const float* __restrict__ xg,    // transposed gates [4H][T*B]
    float* __restrict__ out,         // [T][B][H]
    float* __restrict__ hn,          // [B][H]
    float* __restrict__ cn)          // [B][H]
{
    extern __shared__ float sm[];
    float* h_sm = sm;                // [32][516] padded -> conflict-free LDS.128
    float* w_sm = sm + 32 * 516;     // [4][8][512]

    const int tid  = threadIdx.x;
    const int cta  = blockIdx.x;
    const int jb   = cta & 63;       // 64 j-blocks of 8
    const int bb   = cta >> 6;       // 2 b-blocks of 32
    const int w    = tid >> 5;       // warp -> j within block
    const int lane = tid & 31;       // lane -> b within block
    const int j    = jb * 8 + w;
    const int b    = bb * 32 + lane;
    const int bj   = b * HID + j;

    // preload this CTA's W_hh slice into smem: w_sm[g][jl][k]
    {
        const float4* Wsrc = (const float4*)Whh;
        float4* Wdst = (float4*)w_sm;
#pragma unroll
        for (int idx = tid; idx < 4096; idx += 256) {
            int g   = idx >> 10;          // 1024 float4 per gate
            int rem = idx & 1023;
            int jl  = rem >> 7;           // 128 float4 per row
            int k4  = rem & 127;
            Wdst[idx] = Wsrc[((size_t)(g * HID + jb * 8 + jl) * HID >> 2) + k4];
        }
    }

    float c = c0[bj];
    __stcg(&g_hbuf[0][bj], h0[bj]);

    // per-gate xg base pointers (transposed layout: coalesced lane->b)
    const float* xi = xg + (size_t)(0 * HID + j) * MROWS + b;
    const float* xf = xg + (size_t)(1 * HID + j) * MROWS + b;
    const float* xgp = xg + (size_t)(2 * HID + j) * MROWS + b;
    const float* xo = xg + (size_t)(3 * HID + j) * MROWS + b;

    const ulonglong2* Wi = (const ulonglong2*)&w_sm[0 * 4096 + w * 512];
    const ulonglong2* Wf = (const ulonglong2*)&w_sm[1 * 4096 + w * 512];
    const ulonglong2* Wg = (const ulonglong2*)&w_sm[2 * 4096 + w * 512];
    const ulonglong2* Wo = (const ulonglong2*)&w_sm[3 * 4096 + w * 512];
    const ulonglong2* hp = (const ulonglong2*)&h_sm[lane * 516];

    unsigned expect = 0;
    // barrier: W smem + h_buf[0] init visible before step 0
    __syncthreads();
    if (tid == 0) {
        __threadfence();
        atomicAdd(&g_bar, 1u);
        expect += NCTA;
        while (*((volatile unsigned*)&g_bar) < expect) { }
        __threadfence();
    }
    __syncthreads();

    float h = 0.f;
    for (int t = 0; t < TS; t++) {
        const float* hcur = g_hbuf[t & 1];
        // stage this CTA's 32-batch h slice into smem (L2, coalesced)
#pragma unroll
        for (int idx = tid; idx < 32 * 128; idx += 256) {
            int r  = idx >> 7;
            int c4 = idx & 127;
            float4 v = __ldcg((const float4*)(hcur + (size_t)(bb * 32 + r) * HID) + c4);
            *(float4*)&h_sm[r * 516 + c4 * 4] = v;
        }
        __syncthreads();

        int toff = t * BS;
        unsigned long long ai2 = pack2(__ldg(xi + toff), 0.f);
        unsigned long long af2 = pack2(__ldg(xf + toff), 0.f);
        unsigned long long ag2 = pack2(__ldg(xgp + toff), 0.f);
        unsigned long long ao2 = pack2(__ldg(xo + toff), 0.f);

#pragma unroll 8
        for (int i = 0; i < 128; i++) {
            ulonglong2 hv = hp[i];
            ulonglong2 wi = Wi[i], wf = Wf[i], wg = Wg[i], wo = Wo[i];
            ai2 = fma2(hv.x, wi.x, ai2); ai2 = fma2(hv.y, wi.y, ai2);
            af2 = fma2(hv.x, wf.x, af2); af2 = fma2(hv.y, wf.y, af2);
            ag2 = fma2(hv.x, wg.x, ag2); ag2 = fma2(hv.y, wg.y, ag2);
            ao2 = fma2(hv.x, wo.x, ao2); ao2 = fma2(hv.y, wo.y, ao2);
        }

        float2 pi = unpack2(ai2); float2 pf = unpack2(af2);
        float2 pg = unpack2(ag2); float2 po = unpack2(ao2);
        float ig = sigmoidf_(pi.x + pi.y);
        float fg = sigmoidf_(pf.x + pf.y);
        float gg = tanhf(pg.x + pg.y);
        float og = sigmoidf_(po.x + po.y);
        c = fg * c + ig * gg;
        h = og * tanhf(c);

        out[((size_t)t * BS + b) * HID + j] = h;
        __stcg(&g_hbuf[(t + 1) & 1][bj], h);

        // grid barrier: all h writes of step t visible before step t+1
        __syncthreads();
        if (tid == 0) {
            __threadfence();
            atomicAdd(&g_bar, 1u);
            expect += NCTA;
            while (*((volatile unsigned*)&g_bar) < expect) { }
            __threadfence();
        }
        __syncthreads();
    }

    hn[bj] = h;
    cn[bj] = c;
}

// ---------------------------------------------------------------------------
// Launch: per layer {reset, gemm -> persistent recurrence}.
// Output layout: [layer_out (T,B,H)][h_n (L,B,H)][c_n (L,B,H)]
// ---------------------------------------------------------------------------
extern "C" void kernel_launch(void* const* d_in, const int* in_sizes, int n_in,
                              void* d_out, int out_size)
{
    const float* x    = (const float*)d_in[0];
    const float* h0   = (const float*)d_in[1];
    const float* c0   = (const float*)d_in[2];
    const float* W_ih = (const float*)d_in[3];
    const float* W_hh = (const float*)d_in[4];
    const float* b_ih = (const float*)d_in[5];
    const float* b_hh = (const float*)d_in[6];
    float* out = (float*)d_out;

    cudaFuncSetAttribute(lstm_kernel, cudaFuncAttributeMaxDynamicSharedMemorySize, LSTM_SMEM);

    void* p_out1_v = nullptr;
    cudaGetSymbolAddress(&p_out1_v, g_out1);
    float* p_out1 = (float*)p_out1_v;
    void* p_xg_v = nullptr;
    cudaGetSymbolAddress(&p_xg_v, g_xgates);
    const float* p_xg = (const float*)p_xg_v;

    dim3 ggrid(G4 / 128, MROWS / 128);   // (16, 512)

    // Layer 0
    reset_kernel<<<1, 1>>>();
    gemm_xg<<<ggrid, 256>>>(x, W_ih, b_ih, b_hh);
    lstm_kernel<<<NCTA, 256, LSTM_SMEM>>>(
        W_hh, h0, c0, p_xg,
        p_out1,
        out + TBH,                       // h_n[0]
        out + TBH + 2 * (size_t)BH);     // c_n[0]

    // Layer 1
    reset_kernel<<<1, 1>>>();
    gemm_xg<<<ggrid, 256>>>(p_out1, W_ih + (size_t)G4 * HID, b_ih + G4, b_hh + G4);
    lstm_kernel<<<NCTA, 256, LSTM_SMEM>>>(
        W_hh + (size_t)G4 * HID, h0 + BH, c0 + BH, p_xg,
        out,                             // final layer_out
        out + TBH + (size_t)BH,          // h_n[1]
        out + TBH + 3 * (size_t)BH);     // c_n[1]

    (void)in_sizes; (void)n_in; (void)out_size;
}

// round 3
// speedup vs baseline: 1.6111x; 1.0120x over previous
#include <cuda_runtime.h>
#include <math.h>

// Problem constants
#define TS   1024
#define BS   64
#define HID  512
#define G4   2048
#define NCTA 128
#define MROWS 65536                    // T*B rows of the projection GEMM
#define TBH  ((size_t)TS * BS * HID)   // 33554432
#define BH   (BS * HID)                // 32768
// smem: h tile [32][516] + W_hh slice [8 j][stride 2068] (bank-padded)
#define H_STRIDE 516
#define WJ_STRIDE 2068
#define WG_STRIDE 516
#define LSTM_SMEM ((32 * H_STRIDE + 8 * WJ_STRIDE) * 4)   // 132224 bytes

// Scratch (device globals: the sanctioned allocation-free path)
__device__ float g_xgates[(size_t)G4 * MROWS];     // 512 MB, TRANSPOSED [col][row]
__device__ float g_out1[(size_t)TS * BS * HID];    // 128 MB: layer-0 output sequence
__device__ float g_hbuf[2][BH];                    // double-buffered hidden state
__device__ unsigned int g_bar;                     // grid barrier counter

__global__ void reset_kernel() { g_bar = 0u; }

// ---- packed f32x2 helpers (sm_100+ PTX) -----------------------------------
__device__ __forceinline__ unsigned long long fma2(unsigned long long a,
                                                   unsigned long long b,
                                                   unsigned long long c) {
    unsigned long long d;
    asm("fma.rn.f32x2 %0, %1, %2, %3;" : "=l"(d) : "l"(a), "l"(b), "l"(c));
    return d;
}
__device__ __forceinline__ unsigned long long pack2(float x, float y) {
    unsigned long long d;
    asm("mov.b64 %0, {%1, %2};" : "=l"(d) : "f"(x), "f"(y));
    return d;
}
__device__ __forceinline__ float2 unpack2(unsigned long long v) {
    float2 r;
    asm("mov.b64 {%0, %1}, %2;" : "=f"(r.x), "=f"(r.y) : "l"(v));
    return r;
}

// ---------------------------------------------------------------------------
// Input projection GEMM: C_T[g][m] = sum_k A[m,k] * W[g,k] + b1[g] + b2[g]
// Tile 128x128x16, 256 threads, 8x8 per thread, FFMA2 inner product.
// Output stored TRANSPOSED so the recurrence reads coalesced in batch.
// ---------------------------------------------------------------------------
__global__ __launch_bounds__(256, 2) void gemm_xg(
    const float* __restrict__ A,
    const float* __restrict__ W,
    const float* __restrict__ b1,
    const float* __restrict__ b2)
{
    __shared__ float As[16][128];
    __shared__ float Bs[16][128];
    const int tid = threadIdx.x;
    const int m0 = blockIdx.y * 128;
    const int n0 = blockIdx.x * 128;
    const int tx = tid & 15, ty = tid >> 4;
    const int lr = tid >> 2;
    const int lk = (tid & 3) << 2;

    const float* Ap = A + (size_t)(m0 + lr) * HID + lk;
    const float* Wp = W + (size_t)(n0 + lr) * HID + lk;

    unsigned long long acc2[8][4];
#pragma unroll
    for (int i = 0; i < 8; i++)
#pragma unroll
        for (int j = 0; j < 4; j++) acc2[i][j] = 0ull;

    for (int k0 = 0; k0 < HID; k0 += 16) {
        float4 a0 = *(const float4*)(Ap + k0);
        float4 a1 = *(const float4*)(Ap + (size_t)64 * HID + k0);
        float4 w0 = *(const float4*)(Wp + k0);
        float4 w1 = *(const float4*)(Wp + (size_t)64 * HID + k0);
        __syncthreads();
        As[lk + 0][lr] = a0.x; As[lk + 1][lr] = a0.y; As[lk + 2][lr] = a0.z; As[lk + 3][lr] = a0.w;
        As[lk + 0][lr + 64] = a1.x; As[lk + 1][lr + 64] = a1.y; As[lk + 2][lr + 64] = a1.z; As[lk + 3][lr + 64] = a1.w;
        Bs[lk + 0][lr] = w0.x; Bs[lk + 1][lr] = w0.y; Bs[lk + 2][lr] = w0.z; Bs[lk + 3][lr] = w0.w;
        Bs[lk + 0][lr + 64] = w1.x; Bs[lk + 1][lr + 64] = w1.y; Bs[lk + 2][lr + 64] = w1.z; Bs[lk + 3][lr + 64] = w1.w;
        __syncthreads();
#pragma unroll
        for (int k = 0; k < 16; k++) {
            float a[8];
            *(float4*)&a[0] = *(const float4*)&As[k][ty * 8];
            *(float4*)&a[4] = *(const float4*)&As[k][ty * 8 + 4];
            const ulonglong2* bp = (const ulonglong2*)&Bs[k][tx * 8];
            ulonglong2 t0 = bp[0];
            ulonglong2 t1 = bp[1];
#pragma unroll
            for (int i = 0; i < 8; i++) {
                unsigned long long ad = pack2(a[i], a[i]);
                acc2[i][0] = fma2(ad, t0.x, acc2[i][0]);
                acc2[i][1] = fma2(ad, t0.y, acc2[i][1]);
                acc2[i][2] = fma2(ad, t1.x, acc2[i][2]);
                acc2[i][3] = fma2(ad, t1.y, acc2[i][3]);
            }
        }
    }

    float val[8][8];
#pragma unroll
    for (int i = 0; i < 8; i++)
#pragma unroll
        for (int jp = 0; jp < 4; jp++) {
            float2 p = unpack2(acc2[i][jp]);
            val[i][2 * jp] = p.x;
            val[i][2 * jp + 1] = p.y;
        }
#pragma unroll
    for (int u = 0; u < 8; u++) {
        int col = n0 + tx * 8 + u;
        float bias = b1[col] + b2[col];
        float* Cp = g_xgates + (size_t)col * MROWS + m0 + ty * 8;
        float4 lo, hi;
        lo.x = val[0][u] + bias; lo.y = val[1][u] + bias;
        lo.z = val[2][u] + bias; lo.w = val[3][u] + bias;
        hi.x = val[4][u] + bias; hi.y = val[5][u] + bias;
        hi.z = val[6][u] + bias; hi.w = val[7][u] + bias;
        *(float4*)Cp = lo;
        *(float4*)(Cp + 4) = hi;
    }
}

// ---------------------------------------------------------------------------
// Persistent recurrence. 128 CTAs x 256 threads.
// Warp tile = 8 b x 4 j (lane = bo + 8*jq): h LDS is 1 wavefront (8 unique
// 16B rows), each W LDS is 1 wavefront (4 unique j rows on disjoint banks via
// padded strides). c stays in a register; FFMA2 dot products; x_gates biases
// added AFTER the loop so their DRAM latency is hidden by compute.
// ---------------------------------------------------------------------------
__device__ __forceinline__ float sigmoidf_(float x) { return 1.f / (1.f + expf(-x)); }

__global__ __launch_bounds__(256, 1) void lstm_kernel(
    const float* __restrict__ Whh,   // [4H][H] for this layer
    const float* __restrict__ h0,    // [B][H]
    const float* __restrict__ c0,    // [B][H]
    const float* __restrict__ xg,    // transposed gates [4H][T*B]
    float* __restrict__ out,         // [T][B][H]
    float* __restrict__ hn,          // [B][H]
    float* __restrict__ cn)          // [B][H]
{
    extern __shared__ float sm[];
    float* h_sm = sm;                        // [32][516]
    float* w_sm = sm + 32 * H_STRIDE;        // [8 j][4 g x 516] stride 2068

    const int tid  = threadIdx.x;
    const int cta  = blockIdx.x;
    const int jb   = cta & 63;       // 64 j-blocks of 8
    const int bb   = cta >> 6;       // 2 b-blocks of 32
    const int warp = tid >> 5;
    const int lane = tid & 31;
    const int bq   = warp & 3;       // warp b-quadrant (0..3)
    const int jh   = warp >> 2;      // warp j-half (0..1)
    const int bo   = lane & 7;       // lane b offset (0..7)
    const int jq   = lane >> 3;      // lane j within half (0..3)
    const int bl   = bq * 8 + bo;    // b_local 0..31
    const int jl   = jh * 4 + jq;    // j_local 0..7
    const int j    = jb * 8 + jl;
    const int b    = bb * 32 + bl;
    const int bj   = b * HID + j;

    // preload this CTA's W_hh slice: w_sm[jl][g][k], strides bank-padded
    {
        const float4* Wsrc = (const float4*)Whh;
#pragma unroll
        for (int idx = tid; idx < 4096; idx += 256) {   // float4 units
            int wjl = idx >> 9;            // 512 float4 per j (4g x 128)
            int rem = idx & 511;
            int g   = rem >> 7;
            int k4  = rem & 127;
            *(float4*)&w_sm[wjl * WJ_STRIDE + g * WG_STRIDE + k4 * 4] =
                Wsrc[(((size_t)(g * HID + jb * 8 + wjl)) * HID >> 2) + k4];
        }
    }

    float c = c0[bj];
    __stcg(&g_hbuf[0][bj], h0[bj]);

    // per-gate xg base pointers (transposed layout: coalesced lane->b)
    const float* xi  = xg + (size_t)(0 * HID + j) * MROWS + b;
    const float* xf  = xg + (size_t)(1 * HID + j) * MROWS + b;
    const float* xgp = xg + (size_t)(2 * HID + j) * MROWS + b;
    const float* xo  = xg + (size_t)(3 * HID + j) * MROWS + b;

    const ulonglong2* hp = (const ulonglong2*)&h_sm[bl * H_STRIDE];
    const ulonglong2* W0 = (const ulonglong2*)&w_sm[jl * WJ_STRIDE + 0 * WG_STRIDE];
    const ulonglong2* W1 = (const ulonglong2*)&w_sm[jl * WJ_STRIDE + 1 * WG_STRIDE];
    const ulonglong2* W2 = (const ulonglong2*)&w_sm[jl * WJ_STRIDE + 2 * WG_STRIDE];
    const ulonglong2* W3 = (const ulonglong2*)&w_sm[jl * WJ_STRIDE + 3 * WG_STRIDE];

    unsigned expect = 0;
    __syncthreads();
    if (tid == 0) {
        __threadfence();
        atomicAdd(&g_bar, 1u);
        expect += NCTA;
        while (*((volatile unsigned*)&g_bar) < expect) { }
        __threadfence();
    }
    __syncthreads();

    float h = 0.f;
    for (int t = 0; t < TS; t++) {
        const float* hcur = g_hbuf[t & 1];
        // stage this CTA's 32-batch h slice into smem (L2, coalesced)
#pragma unroll
        for (int idx = tid; idx < 32 * 128; idx += 256) {
            int r  = idx >> 7;
            int c4 = idx & 127;
            float4 v = __ldcg((const float4*)(hcur + (size_t)(bb * 32 + r) * HID) + c4);
            *(float4*)&h_sm[r * H_STRIDE + c4 * 4] = v;
        }
        __syncthreads();

        // issue the 4 gate-bias loads now; consumed only after the loop
        int toff = t * BS;
        float vxi = __ldg(xi + toff);
        float vxf = __ldg(xf + toff);
        float vxg = __ldg(xgp + toff);
        float vxo = __ldg(xo + toff);

        unsigned long long ai2 = 0ull, af2 = 0ull, ag2 = 0ull, ao2 = 0ull;
#pragma unroll 4
        for (int i = 0; i < 128; i++) {
            ulonglong2 hv = hp[i];
            ulonglong2 w0 = W0[i], w1 = W1[i], w2 = W2[i], w3 = W3[i];
            ai2 = fma2(hv.x, w0.x, ai2); ai2 = fma2(hv.y, w0.y, ai2);
            af2 = fma2(hv.x, w1.x, af2); af2 = fma2(hv.y, w1.y, af2);
            ag2 = fma2(hv.x, w2.x, ag2); ag2 = fma2(hv.y, w2.y, ag2);
            ao2 = fma2(hv.x, w3.x, ao2); ao2 = fma2(hv.y, w3.y, ao2);
        }

        float2 pi = unpack2(ai2); float2 pf = unpack2(af2);
        float2 pg = unpack2(ag2); float2 po = unpack2(ao2);
        float ig = sigmoidf_(pi.x + pi.y + vxi);
        float fg = sigmoidf_(pf.x + pf.y + vxf);
        float gg = tanhf(pg.x + pg.y + vxg);
        float og = sigmoidf_(po.x + po.y + vxo);
        c = fg * c + ig * gg;
        h = og * tanhf(c);

        out[((size_t)t * BS + b) * HID + j] = h;
        __stcg(&g_hbuf[(t + 1) & 1][bj], h);

        // grid barrier: all h writes of step t visible before step t+1
        __syncthreads();
        if (tid == 0) {
            __threadfence();
            atomicAdd(&g_bar, 1u);
            expect += NCTA;
            while (*((volatile unsigned*)&g_bar) < expect) { }
            __threadfence();
        }
        __syncthreads();
    }

    hn[bj] = h;
    cn[bj] = c;
}

// ---------------------------------------------------------------------------
// Launch: per layer {reset, gemm -> persistent recurrence}.
// Output layout: [layer_out (T,B,H)][h_n (L,B,H)][c_n (L,B,H)]
// ---------------------------------------------------------------------------
extern "C" void kernel_launch(void* const* d_in, const int* in_sizes, int n_in,
                              void* d_out, int out_size)
{
    const float* x    = (const float*)d_in[0];
    const float* h0   = (const float*)d_in[1];
    const float* c0   = (const float*)d_in[2];
    const float* W_ih = (const float*)d_in[3];
    const float* W_hh = (const float*)d_in[4];
    const float* b_ih = (const float*)d_in[5];
    const float* b_hh = (const float*)d_in[6];
    float* out = (float*)d_out;

    cudaFuncSetAttribute(lstm_kernel, cudaFuncAttributeMaxDynamicSharedMemorySize, LSTM_SMEM);

    void* p_out1_v = nullptr;
    cudaGetSymbolAddress(&p_out1_v, g_out1);
    float* p_out1 = (float*)p_out1_v;
    void* p_xg_v = nullptr;
    cudaGetSymbolAddress(&p_xg_v, g_xgates);
    const float* p_xg = (const float*)p_xg_v;

    dim3 ggrid(G4 / 128, MROWS / 128);   // (16, 512)

    // Layer 0
    reset_kernel<<<1, 1>>>();
    gemm_xg<<<ggrid, 256>>>(x, W_ih, b_ih, b_hh);
    lstm_kernel<<<NCTA, 256, LSTM_SMEM>>>(
        W_hh, h0, c0, p_xg,
        p_out1,
        out + TBH,                       // h_n[0]
        out + TBH + 2 * (size_t)BH);     // c_n[0]

    // Layer 1
    reset_kernel<<<1, 1>>>();
    gemm_xg<<<ggrid, 256>>>(p_out1, W_ih + (size_t)G4 * HID, b_ih + G4, b_hh + G4);
    lstm_kernel<<<NCTA, 256, LSTM_SMEM>>>(
        W_hh + (size_t)G4 * HID, h0 + BH, c0 + BH, p_xg,
        out,                             // final layer_out
        out + TBH + (size_t)BH,          // h_n[1]
        out + TBH + 3 * (size_t)BH);     // c_n[1]

    (void)in_sizes; (void)n_in; (void)out_size;
}

// round 4
// speedup vs baseline: 1.6560x; 1.0279x over previous
#include <cuda_runtime.h>
#include <math.h>

// Problem constants
#define TS   1024
#define BS   64
#define HID  512
#define G4   2048
#define NCTA 128
#define NGRP 64                        // CTAs per barrier group (one per b-half)
#define MROWS 65536                    // T*B rows of the projection GEMM
#define TBH  ((size_t)TS * BS * HID)   // 33554432
#define BH   (BS * HID)                // 32768
// smem: h tile [32][516] + W_hh slice [8 j][stride 2068] (bank-padded)
#define H_STRIDE 516
#define WJ_STRIDE 2068
#define WG_STRIDE 516
#define LSTM_SMEM ((32 * H_STRIDE + 8 * WJ_STRIDE) * 4)   // 132224 bytes

// Scratch (device globals: the sanctioned allocation-free path)
__device__ float g_xgates[(size_t)G4 * MROWS];     // 512 MB, TRANSPOSED [col][row]
__device__ float g_out1[(size_t)TS * BS * HID];    // 128 MB: layer-0 output sequence
__device__ float g_hbuf[2][BH];                    // double-buffered hidden state
__device__ unsigned int g_barG[2];                 // per-group barrier counters

// ---- packed f32x2 helpers (sm_100+ PTX) -----------------------------------
__device__ __forceinline__ unsigned long long fma2(unsigned long long a,
                                                   unsigned long long b,
                                                   unsigned long long c) {
    unsigned long long d;
    asm("fma.rn.f32x2 %0, %1, %2, %3;" : "=l"(d) : "l"(a), "l"(b), "l"(c));
    return d;
}
__device__ __forceinline__ unsigned long long pack2(float x, float y) {
    unsigned long long d;
    asm("mov.b64 %0, {%1, %2};" : "=l"(d) : "f"(x), "f"(y));
    return d;
}
__device__ __forceinline__ float2 unpack2(unsigned long long v) {
    float2 r;
    asm("mov.b64 {%0, %1}, %2;" : "=f"(r.x), "=f"(r.y) : "l"(v));
    return r;
}

// ---- release/acquire barrier primitives (no MEMBAR.GL on critical path) ----
__device__ __forceinline__ void red_release_add(unsigned int* p, unsigned int v) {
    asm volatile("red.release.gpu.global.add.u32 [%0], %1;" :: "l"(p), "r"(v) : "memory");
}
__device__ __forceinline__ unsigned int ld_acquire(const unsigned int* p) {
    unsigned int v;
    asm volatile("ld.acquire.gpu.global.u32 %0, [%1];" : "=r"(v) : "l"(p) : "memory");
    return v;
}

// ---------------------------------------------------------------------------
// Input projection GEMM: C_T[g][m] = sum_k A[m,k] * W[g,k] + b1[g] + b2[g]
// Tile 128x128x16, 256 threads, 8x8 per thread, FFMA2 inner product.
// Output stored TRANSPOSED so the recurrence reads coalesced in batch.
// Also resets the recurrence barrier counters (runs before each lstm pass).
// ---------------------------------------------------------------------------
__global__ __launch_bounds__(256, 2) void gemm_xg(
    const float* __restrict__ A,
    const float* __restrict__ W,
    const float* __restrict__ b1,
    const float* __restrict__ b2)
{
    if (blockIdx.x == 0 && blockIdx.y == 0 && threadIdx.x == 0) {
        g_barG[0] = 0u;
        g_barG[1] = 0u;
    }

    __shared__ float As[16][128];
    __shared__ float Bs[16][128];
    const int tid = threadIdx.x;
    const int m0 = blockIdx.y * 128;
    const int n0 = blockIdx.x * 128;
    const int tx = tid & 15, ty = tid >> 4;
    const int lr = tid >> 2;
    const int lk = (tid & 3) << 2;

    const float* Ap = A + (size_t)(m0 + lr) * HID + lk;
    const float* Wp = W + (size_t)(n0 + lr) * HID + lk;

    unsigned long long acc2[8][4];
#pragma unroll
    for (int i = 0; i < 8; i++)
#pragma unroll
        for (int j = 0; j < 4; j++) acc2[i][j] = 0ull;

    for (int k0 = 0; k0 < HID; k0 += 16) {
        float4 a0 = *(const float4*)(Ap + k0);
        float4 a1 = *(const float4*)(Ap + (size_t)64 * HID + k0);
        float4 w0 = *(const float4*)(Wp + k0);
        float4 w1 = *(const float4*)(Wp + (size_t)64 * HID + k0);
        __syncthreads();
        As[lk + 0][lr] = a0.x; As[lk + 1][lr] = a0.y; As[lk + 2][lr] = a0.z; As[lk + 3][lr] = a0.w;
        As[lk + 0][lr + 64] = a1.x; As[lk + 1][lr + 64] = a1.y; As[lk + 2][lr + 64] = a1.z; As[lk + 3][lr + 64] = a1.w;
        Bs[lk + 0][lr] = w0.x; Bs[lk + 1][lr] = w0.y; Bs[lk + 2][lr] = w0.z; Bs[lk + 3][lr] = w0.w;
        Bs[lk + 0][lr + 64] = w1.x; Bs[lk + 1][lr + 64] = w1.y; Bs[lk + 2][lr + 64] = w1.z; Bs[lk + 3][lr + 64] = w1.w;
        __syncthreads();
#pragma unroll
        for (int k = 0; k < 16; k++) {
            float a[8];
            *(float4*)&a[0] = *(const float4*)&As[k][ty * 8];
            *(float4*)&a[4] = *(const float4*)&As[k][ty * 8 + 4];
            const ulonglong2* bp = (const ulonglong2*)&Bs[k][tx * 8];
            ulonglong2 t0 = bp[0];
            ulonglong2 t1 = bp[1];
#pragma unroll
            for (int i = 0; i < 8; i++) {
                unsigned long long ad = pack2(a[i], a[i]);
                acc2[i][0] = fma2(ad, t0.x, acc2[i][0]);
                acc2[i][1] = fma2(ad, t0.y, acc2[i][1]);
                acc2[i][2] = fma2(ad, t1.x, acc2[i][2]);
                acc2[i][3] = fma2(ad, t1.y, acc2[i][3]);
            }
        }
    }

    float val[8][8];
#pragma unroll
    for (int i = 0; i < 8; i++)
#pragma unroll
        for (int jp = 0; jp < 4; jp++) {
            float2 p = unpack2(acc2[i][jp]);
            val[i][2 * jp] = p.x;
            val[i][2 * jp + 1] = p.y;
        }
#pragma unroll
    for (int u = 0; u < 8; u++) {
        int col = n0 + tx * 8 + u;
        float bias = b1[col] + b2[col];
        float* Cp = g_xgates + (size_t)col * MROWS + m0 + ty * 8;
        float4 lo, hi;
        lo.x = val[0][u] + bias; lo.y = val[1][u] + bias;
        lo.z = val[2][u] + bias; lo.w = val[3][u] + bias;
        hi.x = val[4][u] + bias; hi.y = val[5][u] + bias;
        hi.z = val[6][u] + bias; hi.w = val[7][u] + bias;
        *(float4*)Cp = lo;
        *(float4*)(Cp + 4) = hi;
    }
}

// ---------------------------------------------------------------------------
// Persistent recurrence. 128 CTAs x 256 threads.
// Warp tile = 8 b x 4 j. W_hh slice in smem (loaded once), c in register.
// Barrier: two independent groups (one per b-half), release/acquire, no
// threadfence; out[] DRAM store and next-step xg prefetch overlap the wait.
// ---------------------------------------------------------------------------
__device__ __forceinline__ float sigmoidf_(float x) { return 1.f / (1.f + expf(-x)); }

__global__ __launch_bounds__(256, 1) void lstm_kernel(
    const float* __restrict__ Whh,   // [4H][H] for this layer
    const float* __restrict__ h0,    // [B][H]
    const float* __restrict__ c0,    // [B][H]
    const float* __restrict__ xg,    // transposed gates [4H][T*B]
    float* __restrict__ out,         // [T][B][H]
    float* __restrict__ hn,          // [B][H]
    float* __restrict__ cn)          // [B][H]
{
    extern __shared__ float sm[];
    float* h_sm = sm;                        // [32][516]
    float* w_sm = sm + 32 * H_STRIDE;        // [8 j][4 g x 516] stride 2068

    const int tid  = threadIdx.x;
    const int cta  = blockIdx.x;
    const int jb   = cta & 63;       // 64 j-blocks of 8
    const int bb   = cta >> 6;       // 2 b-blocks of 32 -> barrier group
    const int warp = tid >> 5;
    const int lane = tid & 31;
    const int bq   = warp & 3;
    const int jh   = warp >> 2;
    const int bo   = lane & 7;
    const int jq   = lane >> 3;
    const int bl   = bq * 8 + bo;    // b_local 0..31
    const int jl   = jh * 4 + jq;    // j_local 0..7
    const int j    = jb * 8 + jl;
    const int b    = bb * 32 + bl;
    const int bj   = b * HID + j;

    unsigned int* bar = &g_barG[bb];

    // preload this CTA's W_hh slice: w_sm[jl][g][k], strides bank-padded
    {
        const float4* Wsrc = (const float4*)Whh;
#pragma unroll
        for (int idx = tid; idx < 4096; idx += 256) {   // float4 units
            int wjl = idx >> 9;
            int rem = idx & 511;
            int g   = rem >> 7;
            int k4  = rem & 127;
            *(float4*)&w_sm[wjl * WJ_STRIDE + g * WG_STRIDE + k4 * 4] =
                Wsrc[(((size_t)(g * HID + jb * 8 + wjl)) * HID >> 2) + k4];
        }
    }

    float c = c0[bj];
    __stcg(&g_hbuf[0][bj], h0[bj]);

    // per-gate xg base pointers (transposed layout: coalesced lane->b)
    const float* xi  = xg + (size_t)(0 * HID + j) * MROWS + b;
    const float* xf  = xg + (size_t)(1 * HID + j) * MROWS + b;
    const float* xgp = xg + (size_t)(2 * HID + j) * MROWS + b;
    const float* xo  = xg + (size_t)(3 * HID + j) * MROWS + b;

    const ulonglong2* hp = (const ulonglong2*)&h_sm[bl * H_STRIDE];
    const ulonglong2* W0 = (const ulonglong2*)&w_sm[jl * WJ_STRIDE + 0 * WG_STRIDE];
    const ulonglong2* W1 = (const ulonglong2*)&w_sm[jl * WJ_STRIDE + 1 * WG_STRIDE];
    const ulonglong2* W2 = (const ulonglong2*)&w_sm[jl * WJ_STRIDE + 2 * WG_STRIDE];
    const ulonglong2* W3 = (const ulonglong2*)&w_sm[jl * WJ_STRIDE + 3 * WG_STRIDE];

    // initial barrier: h0 writes of this group visible before step 0
    unsigned expect = 0;
    __syncthreads();
    if (tid == 0) {
        red_release_add(bar, 1u);
        expect += NGRP;
        while (ld_acquire(bar) < expect) { }
    }
    __syncthreads();

    // prefetch step-0 gate biases
    float vxi = __ldg(xi), vxf = __ldg(xf), vxg = __ldg(xgp), vxo = __ldg(xo);

    float h = 0.f;
    for (int t = 0; t < TS; t++) {
        const float* hcur = g_hbuf[t & 1];
        // stage this group's 32-batch h slice into smem (L2, coalesced)
#pragma unroll
        for (int idx = tid; idx < 32 * 128; idx += 256) {
            int r  = idx >> 7;
            int c4 = idx & 127;
            float4 v = __ldcg((const float4*)(hcur + (size_t)(bb * 32 + r) * HID) + c4);
            *(float4*)&h_sm[r * H_STRIDE + c4 * 4] = v;
        }
        __syncthreads();

        unsigned long long ai2 = 0ull, af2 = 0ull, ag2 = 0ull, ao2 = 0ull;
#pragma unroll 4
        for (int i = 0; i < 128; i++) {
            ulonglong2 hv = hp[i];
            ulonglong2 w0 = W0[i], w1 = W1[i], w2 = W2[i], w3 = W3[i];
            ai2 = fma2(hv.x, w0.x, ai2); ai2 = fma2(hv.y, w0.y, ai2);
            af2 = fma2(hv.x, w1.x, af2); af2 = fma2(hv.y, w1.y, af2);
            ag2 = fma2(hv.x, w2.x, ag2); ag2 = fma2(hv.y, w2.y, ag2);
            ao2 = fma2(hv.x, w3.x, ao2); ao2 = fma2(hv.y, w3.y, ao2);
        }

        float2 pi = unpack2(ai2); float2 pf = unpack2(af2);
        float2 pg = unpack2(ag2); float2 po = unpack2(ao2);
        float ig = sigmoidf_(pi.x + pi.y + vxi);
        float fg = sigmoidf_(pf.x + pf.y + vxf);
        float gg = tanhf(pg.x + pg.y + vxg);
        float og = sigmoidf_(po.x + po.y + vxo);
        c = fg * c + ig * gg;
        h = og * tanhf(c);

        // publish h for step t+1, then arrive (release orders the stcg)
        __stcg(&g_hbuf[(t + 1) & 1][bj], h);
        __syncthreads();
        if (tid == 0) {
            red_release_add(bar, 1u);
            expect += NGRP;
        }

        // overlap with barrier wait: out[] DRAM store + next-step xg prefetch
        out[((size_t)t * BS + b) * HID + j] = h;
        if (t + 1 < TS) {
            int toff = (t + 1) * BS;
            vxi = __ldg(xi + toff);
            vxf = __ldg(xf + toff);
            vxg = __ldg(xgp + toff);
            vxo = __ldg(xo + toff);
        }

        if (tid == 0) {
            while (ld_acquire(bar) < expect) { }
        }
        __syncthreads();
    }

    hn[bj] = h;
    cn[bj] = c;
}

// ---------------------------------------------------------------------------
// Launch: per layer {gemm (resets barrier) -> persistent recurrence}.
// Output layout: [layer_out (T,B,H)][h_n (L,B,H)][c_n (L,B,H)]
// ---------------------------------------------------------------------------
extern "C" void kernel_launch(void* const* d_in, const int* in_sizes, int n_in,
                              void* d_out, int out_size)
{
    const float* x    = (const float*)d_in[0];
    const float* h0   = (const float*)d_in[1];
    const float* c0   = (const float*)d_in[2];
    const float* W_ih = (const float*)d_in[3];
    const float* W_hh = (const float*)d_in[4];
    const float* b_ih = (const float*)d_in[5];
    const float* b_hh = (const float*)d_in[6];
    float* out = (float*)d_out;

    cudaFuncSetAttribute(lstm_kernel, cudaFuncAttributeMaxDynamicSharedMemorySize, LSTM_SMEM);

    void* p_out1_v = nullptr;
    cudaGetSymbolAddress(&p_out1_v, g_out1);
    float* p_out1 = (float*)p_out1_v;
    void* p_xg_v = nullptr;
    cudaGetSymbolAddress(&p_xg_v, g_xgates);
    const float* p_xg = (const float*)p_xg_v;

    dim3 ggrid(G4 / 128, MROWS / 128);   // (16, 512)

    // Layer 0
    gemm_xg<<<ggrid, 256>>>(x, W_ih, b_ih, b_hh);
    lstm_kernel<<<NCTA, 256, LSTM_SMEM>>>(
        W_hh, h0, c0, p_xg,
        p_out1,
        out + TBH,                       // h_n[0]
        out + TBH + 2 * (size_t)BH);     // c_n[0]

    // Layer 1
    gemm_xg<<<ggrid, 256>>>(p_out1, W_ih + (size_t)G4 * HID, b_ih + G4, b_hh + G4);
    lstm_kernel<<<NCTA, 256, LSTM_SMEM>>>(
        W_hh + (size_t)G4 * HID, h0 + BH, c0 + BH, p_xg,
        out,                             // final layer_out
        out + TBH + (size_t)BH,          // h_n[1]
        out + TBH + 3 * (size_t)BH);     // c_n[1]

    (void)in_sizes; (void)n_in; (void)out_size;
}